// round 17
// baseline (speedup 1.0000x reference)
#include <cuda_runtime.h>
#include <cuda_fp16.h>
#include <cstdint>

// Problem constants
constexpr int kB = 2, kS = 2048, kH = 512, kNH = 8, kDK = 64;
constexpr int kBH = kB * kNH;

// Scratch (device globals — no allocs).
// g_qh, g_kh: [bh][s][d] fp16.  g_vh: [bh][d][s] fp16 (transposed).
__device__ unsigned short g_qh[kBH * kS * kDK];
__device__ unsigned short g_kh[kBH * kS * kDK];
__device__ unsigned short g_vh[kBH * kS * kDK];
// fp16 pre-converted GEMM inputs: X (q/k/v inputs) and W (weights)
__device__ unsigned short g_x16[3 * kB * kS * kH];   // [which][row 0..4095][k]
__device__ unsigned short g_w16[3 * kH * kH];        // [which][n][k]
// Combined softmax additive plane (fp16): bm[b][q][k] =
//   (bias[b,0,q,k]==0) ? -inf : log2e * mask[b][k]
__device__ unsigned short g_bmh[(size_t)kB * kS * kS];

__device__ __forceinline__ unsigned saddr(const void* p) {
    unsigned a;
    asm("{ .reg .u64 t; cvta.to.shared.u64 t, %1; cvt.u32.u64 %0, t; }" : "=r"(a) : "l"(p));
    return a;
}
__device__ __forceinline__ void ldm_x4(unsigned& r0, unsigned& r1, unsigned& r2, unsigned& r3,
                                       unsigned a) {
    asm volatile("ldmatrix.sync.aligned.m8n8.x4.shared.b16 {%0,%1,%2,%3}, [%4];"
                 : "=r"(r0), "=r"(r1), "=r"(r2), "=r"(r3) : "r"(a));
}

#define CP_ASYNC16(dst, src) \
    asm volatile("cp.async.cg.shared.global [%0], [%1], 16;" :: "r"(dst), "l"(src) : "memory")
#define CP_COMMIT() asm volatile("cp.async.commit_group;" ::: "memory")
#define CP_WAIT1()  asm volatile("cp.async.wait_group 1;" ::: "memory")

// D += A(16x16) * B(16x8), fp16 inputs, fp32 accum.  m16n8k16.
__device__ __forceinline__ void mma_f16(float& d0, float& d1, float& d2, float& d3,
                                        unsigned a0, unsigned a1, unsigned a2, unsigned a3,
                                        unsigned b0, unsigned b1) {
    asm volatile(
        "mma.sync.aligned.m16n8k16.row.col.f32.f16.f16.f32 "
        "{%0,%1,%2,%3}, {%4,%5,%6,%7}, {%8,%9}, {%0,%1,%2,%3};\n"
        : "+f"(d0), "+f"(d1), "+f"(d2), "+f"(d3)
        : "r"(a0), "r"(a1), "r"(a2), "r"(a3), "r"(b0), "r"(b1));
}
__device__ __forceinline__ unsigned packh2(float a, float b) {
    __half2 h = __floats2half2_rn(a, b);
    return *(unsigned*)&h;
}
__device__ __forceinline__ unsigned hadd2u(unsigned a, unsigned b) {
    unsigned r;
    asm("add.rn.f16x2 %0, %1, %2;" : "=r"(r) : "r"(a), "r"(b));
    return r;
}
__device__ __forceinline__ unsigned ex2h2(unsigned x) {
    unsigned r;
    asm("ex2.approx.f16x2 %0, %1;" : "=r"(r) : "r"(x));
    return r;
}

constexpr float kLog2e = 1.44269504088896340736f;
constexpr unsigned kOnesH2 = 0x3C003C00u;   // (half)1.0 x2

// ============================================================================
// Prep: X,W -> fp16 only (bm plane handled inside the proj grid, overlapped).
// ============================================================================
constexpr int XJOBS = 3 * kB * kS * (kH / 4);        // float4 jobs: 1,572,864
constexpr int WJOBS = 3 * kH * (kH / 4);             // 196,608
constexpr int TOTJ  = XJOBS + WJOBS;                 // 1,769,472 = 256*6912

__global__ __launch_bounds__(256) void prep_kernel(
    const float* __restrict__ Xq, const float* __restrict__ Xk, const float* __restrict__ Xv,
    const float* __restrict__ Wq, const float* __restrict__ Wk, const float* __restrict__ Wv)
{
    unsigned idx = blockIdx.x * 256 + threadIdx.x;
    if (idx < XJOBS) {
        const unsigned per = kB * kS * (kH / 4);     // 524,288
        int which = idx / per;
        unsigned rem = idx % per;
        const float* src = (which == 0) ? Xq : (which == 1) ? Xk : Xv;
        float4 v = ((const float4*)src)[rem];
        __half2 a = __floats2half2_rn(v.x, v.y);
        __half2 b = __floats2half2_rn(v.z, v.w);
        ((uint2*)g_x16)[(size_t)which * per + rem] = make_uint2(*(unsigned*)&a, *(unsigned*)&b);
        return;
    }
    idx -= XJOBS;
    if (idx < WJOBS) {
        const unsigned per = kH * (kH / 4);          // 65,536
        int which = idx / per;
        unsigned rem = idx % per;
        const float* src = (which == 0) ? Wq : (which == 1) ? Wk : Wv;
        float4 v = ((const float4*)src)[rem];
        __half2 a = __floats2half2_rn(v.x, v.y);
        __half2 b = __floats2half2_rn(v.z, v.w);
        ((uint2*)g_w16)[(size_t)which * per + rem] = make_uint2(*(unsigned*)&a, *(unsigned*)&b);
    }
}

// ============================================================================
// Projection: Y = X @ W^T + b, fp16 GEMM on pre-converted inputs, tile 128x64,
// cp.async double-buffered pipeline two chunks ahead, ldmatrix feeds.
// q scaled by 0.125*log2e; q/k -> [bh][s][d]; v transposed -> [bh][d][s].
// grid z=3 slice: build the fp16 bm plane (bias==0 -> -inf, else log2e*mask),
// overlapped with the GEMM wave (proj's DRAM pipe is otherwise idle).
// ============================================================================
constexpr int PBM = 128, PBN = 64, PSTH = 40;
constexpr int XTILE = PBM * PSTH;   // halves per X stage (5120)
constexpr int WTILE = PBN * PSTH;   // halves per W stage (2560)
constexpr int NCHUNK = kH / 32;     // 16

__global__ __launch_bounds__(256, 2) void proj_f16(
    const float* __restrict__ bqp, const float* __restrict__ bkp, const float* __restrict__ bvp,
    const float* __restrict__ biasT, const int* __restrict__ maskp)
{
    const int which = blockIdx.z;
    const int tid  = threadIdx.x;

    if (which == 3) {
        // bm plane slice: 256 CTAs x 256 thr x 4 words (word = 32 elements)
        const unsigned short H1 = __half_as_ushort(__float2half_rn(kLog2e));
        unsigned cidx = blockIdx.x + gridDim.x * blockIdx.y;   // 0..255
        unsigned idx = cidx * 256 + tid;                       // 0..65535
        for (int j = 0; j < 4; j++) {
            unsigned w = idx * 4 + j;
            size_t flat = (size_t)w * 32;
            unsigned b = w >> 17;                  // / (2048*64)
            unsigned rem = w & 131071u;
            unsigned k0 = (rem & 63u) * 32u;
            const float4* src = (const float4*)biasT + (flat >> 2);
            const int4* mr = (const int4*)(maskp + b * kS + k0);
            uint4 outv[4];
            unsigned short* us = (unsigned short*)outv;
#pragma unroll
            for (int i = 0; i < 8; i++) {
                float4 v = src[i];
                int4 mm = mr[i];
                us[4*i+0] = (v.x == 0.f) ? (unsigned short)0xFC00 : (mm.x ? H1 : (unsigned short)0);
                us[4*i+1] = (v.y == 0.f) ? (unsigned short)0xFC00 : (mm.y ? H1 : (unsigned short)0);
                us[4*i+2] = (v.z == 0.f) ? (unsigned short)0xFC00 : (mm.z ? H1 : (unsigned short)0);
                us[4*i+3] = (v.w == 0.f) ? (unsigned short)0xFC00 : (mm.w ? H1 : (unsigned short)0);
            }
#pragma unroll
            for (int i2 = 0; i2 < 4; i2++)
                ((uint4*)g_bmh)[(size_t)w * 4 + i2] = outv[i2];
        }
        return;
    }

    __shared__ __half SX[2 * XTILE];
    __shared__ __half SW[2 * WTILE];

    const float* bias = (which == 0) ? bqp : (which == 1) ? bkp : bvp;

    const int warp = tid >> 5, lane = tid & 31;
    const int g = lane >> 2, t = lane & 3;
    const int quad = lane >> 3, r8 = lane & 7;
    const int m0 = blockIdx.x * PBM;
    const int n0 = blockIdx.y * PBN;
    const int rw = warp * 16;

    const unsigned short* xsrc = g_x16 + (size_t)which * (kB * kS * kH) + (size_t)m0 * kH;
    const unsigned short* wsrc = g_w16 + (size_t)which * (kH * kH) + (size_t)n0 * kH;

    const unsigned sx0 = saddr(SX), sw0 = saddr(SW);
    const int fr = tid >> 2, fc = tid & 3;

    auto issue_chunk = [&](int c) {
        const int st = c & 1;
        const int k0 = c * 32;
        const unsigned sxb = sx0 + (unsigned)(st * XTILE) * 2;
        const unsigned swb = sw0 + (unsigned)(st * WTILE) * 2;
#pragma unroll
        for (int i = 0; i < 2; i++) {
            int r = fr + i * 64;
            CP_ASYNC16(sxb + (unsigned)(r * PSTH + fc * 8) * 2,
                       &xsrc[(size_t)r * kH + k0 + fc * 8]);
        }
        CP_ASYNC16(swb + (unsigned)(fr * PSTH + fc * 8) * 2,
                   &wsrc[(size_t)fr * kH + k0 + fc * 8]);
        CP_COMMIT();
    };

    issue_chunk(0);
    issue_chunk(1);

    const unsigned aoff = ((unsigned)((quad & 1) * 8 + r8) * PSTH + (quad >> 1) * 8) * 2;
    const unsigned boff = ((unsigned)((quad >> 1) * 8 + r8) * PSTH + (quad & 1) * 8) * 2;
    const unsigned xA = sx0 + (unsigned)(rw * PSTH) * 2 + aoff;
    const unsigned wB = sw0 + boff;

    float acc[8][4];
#pragma unroll
    for (int j = 0; j < 8; j++) { acc[j][0] = acc[j][1] = acc[j][2] = acc[j][3] = 0.f; }

    for (int c = 0; c < NCHUNK; c++) {
        const int st = c & 1;
        CP_WAIT1();
        __syncthreads();

        const unsigned xa = xA + (unsigned)(st * XTILE) * 2;
        const unsigned wb = wB + (unsigned)(st * WTILE) * 2;
#pragma unroll
        for (int s = 0; s < 2; s++) {
            unsigned a0, a1, a2, a3;
            ldm_x4(a0, a1, a2, a3, xa + s * 32);
#pragma unroll
            for (int m = 0; m < 4; m++) {
                unsigned b0, b1, b2, b3;
                ldm_x4(b0, b1, b2, b3, wb + (unsigned)(16 * m * PSTH) * 2 + s * 32);
                mma_f16(acc[2*m][0], acc[2*m][1], acc[2*m][2], acc[2*m][3],
                        a0, a1, a2, a3, b0, b1);
                mma_f16(acc[2*m+1][0], acc[2*m+1][1], acc[2*m+1][2], acc[2*m+1][3],
                        a0, a1, a2, a3, b2, b3);
            }
        }

        __syncthreads();
        if (c + 2 < NCHUNK) issue_chunk(c + 2);
        else CP_COMMIT();
    }

    const int hh = n0 >> 6;
    const int r0 = m0 + rw + g;
    const int bb = r0 >> 11;
    const int s0 = r0 & (kS - 1);

    if (which != 2) {
        unsigned short* dst = (which == 0) ? g_qh : g_kh;
        const float sc = (which == 0) ? 0.125f * kLog2e : 1.0f;
#pragma unroll
        for (int j = 0; j < 8; j++) {
            int d = 8 * j + 2 * t;
            float bi0 = bias[n0 + d], bi1 = bias[n0 + d + 1];
            size_t o0 = ((size_t)(bb * kNH + hh) * kS + s0) * kDK + d;
            __half2 v0 = __floats2half2_rn((acc[j][0] + bi0) * sc, (acc[j][1] + bi1) * sc);
            __half2 v1 = __floats2half2_rn((acc[j][2] + bi0) * sc, (acc[j][3] + bi1) * sc);
            *(__half2*)&dst[o0]           = v0;
            *(__half2*)&dst[o0 + 8 * kDK] = v1;
        }
    } else {
        asm volatile("cp.async.wait_group 0;" ::: "memory");
        __syncthreads();
        __half* Tr = SX;     // 64 x 136 halves = 8704 <= 2*XTILE
#pragma unroll
        for (int j = 0; j < 8; j++) {
            int d = 8 * j + 2 * t;
            float bi0 = bias[n0 + d], bi1 = bias[n0 + d + 1];
            Tr[d       * 136 + rw + g]     = __float2half_rn(acc[j][0] + bi0);
            Tr[(d + 1) * 136 + rw + g]     = __float2half_rn(acc[j][1] + bi1);
            Tr[d       * 136 + rw + g + 8] = __float2half_rn(acc[j][2] + bi0);
            Tr[(d + 1) * 136 + rw + g + 8] = __float2half_rn(acc[j][3] + bi1);
        }
        __syncthreads();
        const int sbase = m0 & (kS - 1);
#pragma unroll
        for (int i = 0; i < 4; i++) {
            int v = tid + i * 256;
            int rr = v >> 4, cc = v & 15;
            uint4 val = *(const uint4*)&Tr[rr * 136 + cc * 8];
            *(uint4*)&g_vh[((size_t)(bb * kNH + hh) * kDK + rr) * kS + sbase + cc * 8] = val;
        }
    }
}

// ============================================================================
// Flash attention: 256 threads, 8 warps x 16 rows (QT=128), full 64-col rows.
// p = ex2.f16x2(cvt(c) + bm)  [bm fp16 plane: -inf if bias==0, else
// log2e*mask; softmax shift-free since p <= 2^5 fits fp16].  Denominator via
// ones-column mma (exact fp32 row sums, no shuffles).  P in registers;
// ldmatrix feeds; cp.async double-buffered K/V/bm pipeline two tiles ahead.
// ============================================================================
constexpr int QT = 128, KT = 64, ASTH = 72;
constexpr int NTILE = kS / KT;   // 32
constexpr int BMTILE = QT * ASTH;   // halves per bm stage (9216)
constexpr int ATT_SMEM = (QT * ASTH + 2 * KT * ASTH + 2 * kDK * ASTH + 2 * BMTILE) * 2;

__global__ __launch_bounds__(256, 2) void attn_kernel(
    float* __restrict__ out)
{
    extern __shared__ char smraw[];
    __half* Qs = (__half*)smraw;                 // 128 x 72
    __half* Ks = Qs + QT * ASTH;                 // 2 x 64 x 72
    __half* Vs = Ks + 2 * KT * ASTH;             // 2 x 64 x 72  [d][s]
    __half* Bm = Vs + 2 * kDK * ASTH;            // 2 x 128 x 72

    const int tid  = threadIdx.x;
    const int warp = tid >> 5, lane = tid & 31;
    const int g = lane >> 2, t = lane & 3;
    const int quad = lane >> 3, r8 = lane & 7;
    const int qt = blockIdx.x, bh = blockIdx.y;
    const int b = bh >> 3, h = bh & 7;
    const int rw = warp * 16;

    const __half* qptr = (const __half*)g_qh + (size_t)(bh * kS + qt * QT) * kDK;
    const __half* kptr = (const __half*)g_kh + (size_t)bh * kS * kDK;
    const __half* vptr = (const __half*)g_vh + (size_t)bh * kS * kDK;  // [d][s]
    const __half* bmp = (const __half*)g_bmh + ((size_t)b * kS + qt * QT) * kS;

    const int fr = tid >> 3, fc8 = tid & 7;

#pragma unroll
    for (int i = 0; i < 4; i++) {
        int r = fr + i * 32;
        CP_ASYNC16(saddr(Qs) + (unsigned)(r * ASTH + fc8 * 8) * 2,
                   &qptr[(size_t)r * kDK + fc8 * 8]);
    }
    CP_COMMIT();

    const unsigned ks0 = saddr(Ks), vs0 = saddr(Vs), bm0 = saddr(Bm);
    auto issue_tile = [&](int i) {
        const int st = i & 1;
        const int kv0 = i * KT;
        const unsigned ksb = ks0 + (unsigned)(st * KT * ASTH) * 2;
        const unsigned vsb = vs0 + (unsigned)(st * kDK * ASTH) * 2;
        const unsigned bmb = bm0 + (unsigned)(st * BMTILE) * 2;
#pragma unroll
        for (int ii = 0; ii < 2; ii++) {
            int r = fr + ii * 32;
            CP_ASYNC16(ksb + (unsigned)(r * ASTH + fc8 * 8) * 2,
                       &kptr[(size_t)(kv0 + r) * kDK + fc8 * 8]);
            CP_ASYNC16(vsb + (unsigned)(r * ASTH + fc8 * 8) * 2,
                       &vptr[(size_t)r * kS + kv0 + fc8 * 8]);
        }
#pragma unroll
        for (int ii = 0; ii < 4; ii++) {
            int r = fr + ii * 32;
            CP_ASYNC16(bmb + (unsigned)(r * ASTH + fc8 * 8) * 2,
                       &bmp[(size_t)r * kS + kv0 + fc8 * 8]);
        }
        CP_COMMIT();
    };

    issue_tile(0);
    issue_tile(1);

    const unsigned qoff = ((unsigned)((quad & 1) * 8 + r8) * ASTH + (quad >> 1) * 8) * 2;
    const unsigned boff = ((unsigned)((quad >> 1) * 8 + r8) * ASTH + (quad & 1) * 8) * 2;

    float o[8][4];
#pragma unroll
    for (int j = 0; j < 8; j++) { o[j][0] = o[j][1] = o[j][2] = o[j][3] = 0.f; }
    float osum[4] = {0.f, 0.f, 0.f, 0.f};
    unsigned qf[4][4];
    bool qf_done = false;

    for (int i = 0; i < NTILE; i++) {
        const int st = i & 1;

        CP_WAIT1();
        __syncthreads();

        if (!qf_done) {
            unsigned qb = saddr(Qs) + (unsigned)(rw * ASTH) * 2 + qoff;
#pragma unroll
            for (int kk = 0; kk < 4; kk++)
                ldm_x4(qf[kk][0], qf[kk][1], qf[kk][2], qf[kk][3], qb + kk * 32);
            qf_done = true;
        }

        const unsigned kb = ks0 + (unsigned)(st * KT * ASTH) * 2 + boff;
        const unsigned vb = vs0 + (unsigned)(st * kDK * ASTH) * 2 + boff;
        const unsigned bmA = bm0 + (unsigned)(st * BMTILE) * 2 + (unsigned)(rw * ASTH) * 2 + qoff;

        // S = Q * K^T  (scores in log2 units)
        float c[8][4];
#pragma unroll
        for (int j = 0; j < 8; j++) { c[j][0] = c[j][1] = c[j][2] = c[j][3] = 0.f; }
#pragma unroll
        for (int kk = 0; kk < 4; kk++) {
#pragma unroll
            for (int m = 0; m < 4; m++) {
                unsigned b0, b1, b2, b3;
                ldm_x4(b0, b1, b2, b3, kb + (unsigned)(16 * m * ASTH) * 2 + kk * 32);
                mma_f16(c[2*m][0], c[2*m][1], c[2*m][2], c[2*m][3],
                        qf[kk][0], qf[kk][1], qf[kk][2], qf[kk][3], b0, b1);
                mma_f16(c[2*m+1][0], c[2*m+1][1], c[2*m+1][2], c[2*m+1][3],
                        qf[kk][0], qf[kk][1], qf[kk][2], qf[kk][3], b2, b3);
            }
        }

        // P = ex2.f16x2(cvt(c) + bm); denominator via ones-column mma
        unsigned pf[4][4];
#pragma unroll
        for (int kk = 0; kk < 4; kk++) {
            unsigned m0_, m1_, m2_, m3_;
            ldm_x4(m0_, m1_, m2_, m3_, bmA + kk * 32);
            pf[kk][0] = ex2h2(hadd2u(packh2(c[2*kk][0],   c[2*kk][1]),   m0_));
            pf[kk][1] = ex2h2(hadd2u(packh2(c[2*kk][2],   c[2*kk][3]),   m1_));
            pf[kk][2] = ex2h2(hadd2u(packh2(c[2*kk+1][0], c[2*kk+1][1]), m2_));
            pf[kk][3] = ex2h2(hadd2u(packh2(c[2*kk+1][2], c[2*kk+1][3]), m3_));
            mma_f16(osum[0], osum[1], osum[2], osum[3],
                    pf[kk][0], pf[kk][1], pf[kk][2], pf[kk][3], kOnesH2, kOnesH2);
        }

        // O += P * V  (A from registers, B via ldmatrix from Vs [d][s])
#pragma unroll
        for (int kk = 0; kk < 4; kk++) {
#pragma unroll
            for (int m = 0; m < 4; m++) {
                unsigned b0, b1, b2, b3;
                ldm_x4(b0, b1, b2, b3, vb + (unsigned)(16 * m * ASTH) * 2 + kk * 32);
                mma_f16(o[2*m][0], o[2*m][1], o[2*m][2], o[2*m][3],
                        pf[kk][0], pf[kk][1], pf[kk][2], pf[kk][3], b0, b1);
                mma_f16(o[2*m+1][0], o[2*m+1][1], o[2*m+1][2], o[2*m+1][3],
                        pf[kk][0], pf[kk][1], pf[kk][2], pf[kk][3], b2, b3);
            }
        }

        __syncthreads();     // all readers done with stage st
        if (i + 2 < NTILE) issue_tile(i + 2);
        else CP_COMMIT();
    }

    // osum columns are all identical row sums: osum[0] -> row g, osum[2] -> row g+8
    const float inv0 = 1.f / osum[0], inv1 = 1.f / osum[2];
    const int q0 = qt * QT + rw + g;
    float* orow0 = out + ((size_t)b * kS + q0) * kH + h * kDK;
    float* orow1 = orow0 + (size_t)8 * kH;
#pragma unroll
    for (int j = 0; j < 8; j++) {
        int cc = 8 * j + 2 * t;
        *(float2*)&orow0[cc] = make_float2(o[j][0] * inv0, o[j][1] * inv0);
        *(float2*)&orow1[cc] = make_float2(o[j][2] * inv1, o[j][3] * inv1);
    }
}

// ============================================================================
extern "C" void kernel_launch(void* const* d_in, const int* in_sizes, int n_in,
                              void* d_out, int out_size) {
    const float* query = (const float*)d_in[0];
    const float* key   = (const float*)d_in[1];
    const float* value = (const float*)d_in[2];
    const float* bias  = (const float*)d_in[3];
    const int*   mask  = (const int*)d_in[4];
    const float* Wq    = (const float*)d_in[5];
    const float* bq    = (const float*)d_in[6];
    const float* Wk    = (const float*)d_in[7];
    const float* bk    = (const float*)d_in[8];
    const float* Wv    = (const float*)d_in[9];
    const float* bv    = (const float*)d_in[10];
    float* out = (float*)d_out;

    cudaFuncSetAttribute(attn_kernel, cudaFuncAttributeMaxDynamicSharedMemorySize, ATT_SMEM);

    prep_kernel<<<TOTJ / 256, 256>>>(query, key, value, Wq, Wk, Wv);

    dim3 pgrid(kB * kS / PBM, kH / PBN, 4);   // z=3: bm-plane slice
    proj_f16<<<pgrid, 256>>>(bq, bk, bv, bias, mask);

    attn_kernel<<<dim3(kS / QT, kBH), 256, ATT_SMEM>>>(out);
}